// round 15
// baseline (speedup 1.0000x reference)
#include <cuda_runtime.h>

#define DIM 192
#define PLANE (DIM * DIM)
#define SMOOTH_DR 1e-5f
#define N_TOTAL (2.0 * 192.0 * 192.0 * 192.0)

#define BXT 32              // threads in x; 2 x each -> 64 x per block
#define BYT 6               // threads in y; 3 rows each (18 rows: 16 out + 2 halo)
#define NTHR (BXT * BYT)    // 192
#define ZCHUNK 24
#define GX 3
#define GY 12
#define GZ 16               // 2 batches * 8 z-chunks
#define NBLK (GX * GY * GZ) // 576

typedef unsigned long long u64;

__device__ double g_acc = 0.0;
__device__ unsigned int g_count = 0u;

// ---- packed f32x2 helpers (sm_103a) ----
__device__ __forceinline__ u64 pk2(float lo, float hi) {
    u64 r; asm("mov.b64 %0, {%1, %2};" : "=l"(r) : "f"(lo), "f"(hi)); return r;
}
__device__ __forceinline__ void upk2(u64 v, float& lo, float& hi) {
    asm("mov.b64 {%0, %1}, %2;" : "=f"(lo), "=f"(hi) : "l"(v));
}
__device__ __forceinline__ u64 f2add(u64 a, u64 b) {
    u64 d; asm("add.rn.f32x2 %0, %1, %2;" : "=l"(d) : "l"(a), "l"(b)); return d;
}
__device__ __forceinline__ u64 f2mul(u64 a, u64 b) {
    u64 d; asm("mul.rn.f32x2 %0, %1, %2;" : "=l"(d) : "l"(a), "l"(b)); return d;
}
__device__ __forceinline__ u64 f2fma(u64 a, u64 b, u64 c) {
    u64 d; asm("fma.rn.f32x2 %0, %1, %2, %3;" : "=l"(d) : "l"(a), "l"(b), "l"(c)); return d;
}

// one plane's raw data for 3 rows: float2 of pred/targ + one combined edge scalar each
struct PL {
    float a1[3], a2[3];   // pred x0, x0+1
    float b1[3], b2[3];   // targ x0, x0+1
    float ea[3], eb[3];   // edge scalar (x0-1 for lx lane, x0+2 for rx lane)
};

__global__ void __launch_bounds__(NTHR, 3)
ncc_kernel(const float* __restrict__ pred, const float* __restrict__ targ,
           float* __restrict__ out)
{
    // double-buffered zx-sums: [parity][quantity][rowsel r0/r2][ty][tx]
    __shared__ u64 s[2][5][2][BYT][BXT];   // 30720 B
    __shared__ float wsum[BYT];

    const int tx = threadIdx.x;
    const int ty = threadIdx.y;
    const int bx = blockIdx.x;
    const int x0 = bx * 64 + tx * 2;            // 0..190
    const int y0 = blockIdx.y * 16 + 3 * ty - 1; // base row of owned triple: -1..190
    const int zb = blockIdx.z;
    const int b  = zb >> 3;
    const int zc = (zb & 7) * ZCHUNK;           // 0..168

    const bool yok0 = (y0 >= 0);
    const bool yok2 = (y0 + 2 < DIM);
    const bool lx = (tx == 0), rx = (tx == BXT - 1);
    const bool pe = (lx && bx > 0) || (rx && bx < GX - 1);
    const int  eoff = lx ? -1 : 2;

    const float* pb = pred + b * (DIM * DIM * DIM);
    const float* tb = targ + b * (DIM * DIM * DIM);

    const u64 NEGC = pk2(-1.f / 27.f, -1.f / 27.f);
    const u64 DRP  = pk2(SMOOTH_DR, SMOOTH_DR);

    // rolling z-ring per owned row: rA = xs(z), rP = xs(z-1)+xs(z)
    u64 rA[3][5], rP[3][5];
#pragma unroll
    for (int r = 0; r < 3; ++r)
#pragma unroll
        for (int q = 0; q < 5; ++q) { rA[r][q] = 0ull; rP[r][q] = 0ull; }

    float acc = 0.f;

    auto loadp = [&](int o, bool zok, PL& L) {
#pragma unroll
        for (int r = 0; r < 3; ++r) {
            const bool ok = zok && (r == 0 ? yok0 : (r == 2 ? yok2 : true));
            const int oo = o + r * DIM;
            float2 v = make_float2(0.f, 0.f), w = make_float2(0.f, 0.f);
            if (ok) {
                v = __ldg((const float2*)(pb + oo));
                w = __ldg((const float2*)(tb + oo));
            }
            L.a1[r] = v.x; L.a2[r] = v.y;
            L.b1[r] = w.x; L.b2[r] = w.y;
            float e1 = 0.f, e2 = 0.f;
            if (pe && ok) { e1 = __ldg(pb + oo + eoff); e2 = __ldg(tb + oo + eoff); }
            L.ea[r] = e1; L.eb[r] = e2;
        }
    };

    // process one row: x-window sums, z-ring advance; zs receives 3-plane z-sum
    auto procrow = [&](const PL& L, int r, u64* zs) {
        const float p1 = L.a1[r], p2 = L.a2[r], t1 = L.b1[r], t2 = L.b2[r];
        float p0 = __shfl_up_sync(0xffffffffu, p2, 1);
        float p3 = __shfl_down_sync(0xffffffffu, p1, 1);
        float t0 = __shfl_up_sync(0xffffffffu, t2, 1);
        float t3 = __shfl_down_sync(0xffffffffu, t1, 1);
        if (lx) { p0 = L.ea[r]; t0 = L.eb[r]; }
        if (rx) { p3 = L.ea[r]; t3 = L.eb[r]; }

        const u64 A = pk2(p0, p1), M = pk2(p1, p2), B = pk2(p2, p3);
        const u64 C = pk2(t0, t1), N = pk2(t1, t2), D = pk2(t2, t3);

        u64 xs[5];
        xs[0] = f2add(f2add(A, M), B);
        xs[1] = f2add(f2add(C, N), D);
        xs[2] = f2fma(A, A, f2fma(M, M, f2mul(B, B)));
        xs[3] = f2fma(C, C, f2fma(N, N, f2mul(D, D)));
        xs[4] = f2fma(A, C, f2fma(M, N, f2mul(B, D)));
#pragma unroll
        for (int q = 0; q < 5; ++q) {
            zs[q]    = f2add(rP[r][q], xs[q]);
            rP[r][q] = f2add(rA[r][q], xs[q]);
            rA[r][q] = xs[q];
        }
    };

    auto nccS = [&](const u64* S) {
        const u64 SIm = f2mul(S[0], NEGC);
        const u64 SJm = f2mul(S[1], NEGC);
        const u64 cr  = f2fma(SIm, S[1], S[4]);
        const u64 pv  = f2fma(SIm, S[0], S[2]);
        const u64 tv  = f2fma(SJm, S[1], S[3]);
        const u64 num = f2mul(cr, cr);
        const u64 den = f2fma(tv, pv, DRP);
        float n0, n1, d0, d1;
        upk2(num, n0, n1); upk2(den, d0, d1);
        acc += __fdividef(n0, d0) + __fdividef(n1, d1);
    };

    // ---- prologue: planes zc-2, zc-1, zc (ring fill, no output) ----
    int off = (zc - 2) * PLANE + y0 * DIM + x0;
#pragma unroll
    for (int k = 0; k < 3; ++k) {
        PL L;
        loadp(off, (zc - 2 + k) >= 0, L);
        u64 d0[5], d1[5], d2[5];           // unused -> zs adds DCE'd
        procrow(L, 0, d0);
        procrow(L, 1, d1);
        procrow(L, 2, d2);
        off += PLANE;
    }

    // ---- main: 24 output planes, consume plane zc+1+it, output plane zc+it ----
    PL cur;
    loadp(off, true, cur);                 // plane zc+1, always in-bounds

#pragma unroll 2
    for (int it = 0; it < 24; ++it) {
        PL nxt;
        const bool nz = (it < 23) && (zc + 2 + it < DIM);
        const int noff = off + PLANE;
        loadp(noff, nz, nxt);              // issued early; in flight across barrier

        u64 zs0[5], zs1[5], zs2[5];
        procrow(cur, 0, zs0);
        procrow(cur, 1, zs1);
        procrow(cur, 2, zs2);

        const int p = it & 1;              // static under unroll 2
        u64* wb = &s[p][0][0][ty][tx];     // q-stride 384, rowsel-stride 192 (u64)
#pragma unroll
        for (int q = 0; q < 5; ++q) {
            wb[q * 384]       = zs0[q];
            wb[q * 384 + 192] = zs2[q];
        }
        __syncthreads();

        {   // middle output row (3ty): fully register-resident
            u64 S[5];
#pragma unroll
            for (int q = 0; q < 5; ++q) S[q] = f2add(f2add(zs0[q], zs1[q]), zs2[q]);
            nccS(S);
        }
        if (ty > 0) {                      // row 3ty-1: needs (ty-1)'s r2 from smem
            const u64* rb = &s[p][0][1][ty - 1][tx];
            u64 S[5];
#pragma unroll
            for (int q = 0; q < 5; ++q) S[q] = f2add(rb[q * 384], f2add(zs0[q], zs1[q]));
            nccS(S);
        }
        if (ty < BYT - 1) {                // row 3ty+1: needs (ty+1)'s r0 from smem
            const u64* rb = &s[p][0][0][ty + 1][tx];
            u64 S[5];
#pragma unroll
            for (int q = 0; q < 5; ++q) S[q] = f2add(f2add(zs1[q], zs2[q]), rb[q * 384]);
            nccS(S);
        }

        cur = nxt;                         // renamed under unroll
        off = noff;
    }

    // ---- block reduction + fused finalize ----
#pragma unroll
    for (int o = 16; o > 0; o >>= 1)
        acc += __shfl_down_sync(0xffffffffu, acc, o);
    if (tx == 0) wsum[ty] = acc;           // warp id == ty (blockDim.x == 32)
    __syncthreads();

    if (tx == 0 && ty == 0) {
        float bs = 0.f;
#pragma unroll
        for (int w = 0; w < BYT; ++w) bs += wsum[w];
        atomicAdd(&g_acc, (double)bs);
        __threadfence();
        unsigned t = atomicAdd(&g_count, 1u);
        if (t == NBLK - 1) {               // last block: finalize + reset for replay
            double total = *((volatile double*)&g_acc);
            out[0] = (float)(-total / N_TOTAL);
            g_acc = 0.0;
            g_count = 0u;
        }
    }
}

extern "C" void kernel_launch(void* const* d_in, const int* in_sizes, int n_in,
                              void* d_out, int out_size) {
    const float* pred = (const float*)d_in[0];
    const float* targ = (const float*)d_in[1];
    float* out = (float*)d_out;

    dim3 block(BXT, BYT);
    dim3 grid(GX, GY, GZ);
    ncc_kernel<<<grid, block>>>(pred, targ, out);
}

// round 17
// speedup vs baseline: 2.3199x; 2.3199x over previous
#include <cuda_runtime.h>

#define DIM 192
#define PLANE (DIM * DIM)
#define SMOOTH_DR 1e-5f
#define N_TOTAL (2.0 * 192.0 * 192.0 * 192.0)

#define BXT 32              // threads in x; 2 x each -> 64 x per block
#define BYT 9               // threads in y; 2 rows each (18 rows: 16 out + 2 halo)
#define NTHR (BXT * BYT)    // 288
#define ZCHUNK 24
#define GX 3
#define GY 12
#define GZ 16               // 2 batches * 8 z-chunks
#define NBLK (GX * GY * GZ) // 576

typedef unsigned long long u64;

__device__ double g_acc = 0.0;
__device__ unsigned int g_count = 0u;

// ---- packed f32x2 helpers (sm_103a) ----
__device__ __forceinline__ u64 pk2(float lo, float hi) {
    u64 r; asm("mov.b64 %0, {%1, %2};" : "=l"(r) : "f"(lo), "f"(hi)); return r;
}
__device__ __forceinline__ void upk2(u64 v, float& lo, float& hi) {
    asm("mov.b64 {%0, %1}, %2;" : "=f"(lo), "=f"(hi) : "l"(v));
}
__device__ __forceinline__ u64 f2add(u64 a, u64 b) {
    u64 d; asm("add.rn.f32x2 %0, %1, %2;" : "=l"(d) : "l"(a), "l"(b)); return d;
}
__device__ __forceinline__ u64 f2mul(u64 a, u64 b) {
    u64 d; asm("mul.rn.f32x2 %0, %1, %2;" : "=l"(d) : "l"(a), "l"(b)); return d;
}
__device__ __forceinline__ u64 f2fma(u64 a, u64 b, u64 c) {
    u64 d; asm("fma.rn.f32x2 %0, %1, %2, %3;" : "=l"(d) : "l"(a), "l"(b), "l"(c)); return d;
}

__global__ void __launch_bounds__(NTHR, 2)
ncc_kernel(const float* __restrict__ pred, const float* __restrict__ targ,
           float* __restrict__ out)
{
    // double-buffered zx-sums: [parity][quantity][rowsel a/b][ty][tx]
    __shared__ u64 s[2][5][2][BYT][BXT];
    __shared__ float wsum[BYT];

    const int tx = threadIdx.x;
    const int ty = threadIdx.y;
    const int bx = blockIdx.x;
    const int x0 = bx * 64 + tx * 2;             // 0..190
    const int ya = blockIdx.y * 16 + 2 * ty - 1; // row a: -1..191
    const int zb = blockIdx.z;
    const int b  = zb >> 3;
    const int zc = (zb & 7) * ZCHUNK;            // 0..168

    const bool yok0 = (ya >= 0);
    const bool yok1 = (ya + 1 < DIM);
    const bool lx = (tx == 0), rx = (tx == BXT - 1);
    const bool pe = (lx && bx > 0) || (rx && bx < GX - 1);
    const int  eoff = lx ? -1 : 2;

    const float* pb = pred + b * (DIM * DIM * DIM);
    const float* tb = targ + b * (DIM * DIM * DIM);

    const u64 NEGC = pk2(-1.f / 27.f, -1.f / 27.f);
    const u64 DRP  = pk2(SMOOTH_DR, SMOOTH_DR);

    // rolling z-ring per owned row: rA = xs(z), rP = xs(z-1)+xs(z)
    u64 rA0[5], rP0[5], rA1[5], rP1[5];
#pragma unroll
    for (int q = 0; q < 5; ++q) { rA0[q] = 0ull; rP0[q] = 0ull; rA1[q] = 0ull; rP1[q] = 0ull; }

    float acc = 0.f;

    // flat parity-indexed plane buffers (constant-indexed after unroll)
    float pa1[2], pa2[2], pb1_[2], pb2_[2];   // pred rows a,b
    float ta1[2], ta2[2], tb1_[2], tb2_[2];   // targ rows a,b
    float epa[2], epb[2], eta[2], etb[2];     // combined edge scalars

    auto loadp = [&](int o, bool zok, int k) {
        const bool ok0 = zok && yok0;
        const bool ok1 = zok && yok1;
        float2 v0 = make_float2(0.f, 0.f), w0 = make_float2(0.f, 0.f);
        float2 v1 = make_float2(0.f, 0.f), w1 = make_float2(0.f, 0.f);
        if (ok0) {
            v0 = __ldg((const float2*)(pb + o));
            w0 = __ldg((const float2*)(tb + o));
        }
        if (ok1) {
            v1 = __ldg((const float2*)(pb + o + DIM));
            w1 = __ldg((const float2*)(tb + o + DIM));
        }
        pa1[k] = v0.x; pa2[k] = v0.y; ta1[k] = w0.x; ta2[k] = w0.y;
        pb1_[k] = v1.x; pb2_[k] = v1.y; tb1_[k] = w1.x; tb2_[k] = w1.y;
        float e0 = 0.f, e1 = 0.f, e2 = 0.f, e3 = 0.f;
        if (pe && ok0) { e0 = __ldg(pb + o + eoff);       e2 = __ldg(tb + o + eoff); }
        if (pe && ok1) { e1 = __ldg(pb + o + DIM + eoff); e3 = __ldg(tb + o + DIM + eoff); }
        epa[k] = e0; epb[k] = e1; eta[k] = e2; etb[k] = e3;
    };

    // x-window sums + z-ring advance for one row; zs receives the 3-plane z-sum
    auto xsrow = [&](float p1, float p2, float t1, float t2, float ep, float et,
                     u64* rAr, u64* rPr, u64* zs) {
        float p0 = __shfl_up_sync(0xffffffffu, p2, 1);
        float p3 = __shfl_down_sync(0xffffffffu, p1, 1);
        float t0 = __shfl_up_sync(0xffffffffu, t2, 1);
        float t3 = __shfl_down_sync(0xffffffffu, t1, 1);
        if (lx) { p0 = ep; t0 = et; }
        if (rx) { p3 = ep; t3 = et; }

        const u64 A = pk2(p0, p1), M = pk2(p1, p2), B = pk2(p2, p3);
        const u64 C = pk2(t0, t1), N = pk2(t1, t2), D = pk2(t2, t3);

        u64 xs[5];
        xs[0] = f2add(f2add(A, M), B);
        xs[1] = f2add(f2add(C, N), D);
        xs[2] = f2fma(A, A, f2fma(M, M, f2mul(B, B)));
        xs[3] = f2fma(C, C, f2fma(N, N, f2mul(D, D)));
        xs[4] = f2fma(A, C, f2fma(M, N, f2mul(B, D)));
#pragma unroll
        for (int q = 0; q < 5; ++q) {
            zs[q]   = f2add(rPr[q], xs[q]);
            rPr[q]  = f2add(rAr[q], xs[q]);
            rAr[q]  = xs[q];
        }
    };

    auto nccS = [&](const u64* S) {
        const u64 SIm = f2mul(S[0], NEGC);
        const u64 SJm = f2mul(S[1], NEGC);
        const u64 cr  = f2fma(SIm, S[1], S[4]);
        const u64 pv  = f2fma(SIm, S[0], S[2]);
        const u64 tv  = f2fma(SJm, S[1], S[3]);
        const u64 num = f2mul(cr, cr);
        const u64 den = f2fma(tv, pv, DRP);
        float n0, n1, d0, d1;
        upk2(num, n0, n1); upk2(den, d0, d1);
        acc += __fdividef(n0, d0) + __fdividef(n1, d1);
    };

    // ---- prologue: planes zc-2, zc-1, zc (ring fill, no output) ----
    int off = (zc - 2) * PLANE + ya * DIM + x0;
#pragma unroll
    for (int k = 0; k < 3; ++k) {
        loadp(off, (zc - 2 + k) >= 0, 0);
        u64 d0[5], d1[5];   // unused z-sums -> DCE'd
        xsrow(pa1[0], pa2[0], ta1[0], ta2[0], epa[0], eta[0], rA0, rP0, d0);
        xsrow(pb1_[0], pb2_[0], tb1_[0], tb2_[0], epb[0], etb[0], rA1, rP1, d1);
        off += PLANE;
    }

    // ---- main: consume plane zc+1+it, output plane zc+it, it = 0..23 ----
    loadp(off, true, 0);   // plane zc+1 (always <= 169, in bounds)

#pragma unroll 2
    for (int it = 0; it < 24; ++it) {
        const int c = it & 1;        // consume buffer (static under unroll 2)
        const int n = c ^ 1;         // prefetch buffer
        if (it < 23)
            loadp(off + PLANE, (zc + 2 + it) < DIM, n);   // in flight across barrier

        u64 zs0[5], zs1[5];
        xsrow(pa1[c], pa2[c], ta1[c], ta2[c], epa[c], eta[c], rA0, rP0, zs0);
        xsrow(pb1_[c], pb2_[c], tb1_[c], tb2_[c], epb[c], etb[c], rA1, rP1, zs1);

        u64* wb = &s[c][0][0][ty][tx];    // q-stride 2*BYT*BXT=576, rowsel-stride 288 (u64)
#pragma unroll
        for (int q = 0; q < 5; ++q) {
            wb[q * 576]       = zs0[q];
            wb[q * 576 + 288] = zs1[q];
        }
        __syncthreads();

        if (ty >= 1) {                     // output row ya: needs (ty-1)'s b row
            const u64* rb = &s[c][0][1][ty - 1][tx];
            u64 S[5];
#pragma unroll
            for (int q = 0; q < 5; ++q)
                S[q] = f2add(rb[q * 576], f2add(zs0[q], zs1[q]));
            nccS(S);
        }
        if (ty < BYT - 1) {                // output row ya+1: needs (ty+1)'s a row
            const u64* rb = &s[c][0][0][ty + 1][tx];
            u64 S[5];
#pragma unroll
            for (int q = 0; q < 5; ++q)
                S[q] = f2add(f2add(zs0[q], zs1[q]), rb[q * 576]);
            nccS(S);
        }

        off += PLANE;
    }

    // ---- block reduction + fused finalize ----
#pragma unroll
    for (int o = 16; o > 0; o >>= 1)
        acc += __shfl_down_sync(0xffffffffu, acc, o);
    if (tx == 0) wsum[ty] = acc;           // warp id == ty (blockDim.x == 32)
    __syncthreads();

    if (tx == 0 && ty == 0) {
        float bs = 0.f;
#pragma unroll
        for (int w = 0; w < BYT; ++w) bs += wsum[w];
        atomicAdd(&g_acc, (double)bs);
        __threadfence();
        unsigned t = atomicAdd(&g_count, 1u);
        if (t == NBLK - 1) {               // last block: finalize + reset for replay
            double total = *((volatile double*)&g_acc);
            out[0] = (float)(-total / N_TOTAL);
            g_acc = 0.0;
            g_count = 0u;
        }
    }
}

extern "C" void kernel_launch(void* const* d_in, const int* in_sizes, int n_in,
                              void* d_out, int out_size) {
    const float* pred = (const float*)d_in[0];
    const float* targ = (const float*)d_in[1];
    float* out = (float*)d_out;

    dim3 block(BXT, BYT);
    dim3 grid(GX, GY, GZ);
    ncc_kernel<<<grid, block>>>(pred, targ, out);
}